// round 1
// baseline (speedup 1.0000x reference)
#include <cuda_runtime.h>

#define NN 409600
#define GG 1024
#define DD 300
#define D4 75          // DD/4 float4 per row
#define TOT4 (NN * D4) // 30,720,000

static __constant__ float EPS_MAX_F = 1e-12f;
static __constant__ float EPS_BN_F  = 1e-5f;

// ---- scratch (allocation-free: __device__ globals) ----
__device__ float g_seg_sum[GG * DD];
__device__ float g_seg_sq [GG * DD];
__device__ int   g_seg_max[GG * DD];   // float bits (values >= 0, int-monotone)
__device__ float g_inv1[GG];           // 1/sqrt(seg scalar max)  -> multiply x by this
__device__ float g_inv2[GG];           // 1/(seg scalar max)      -> for sum of squares
__device__ __align__(16) float g_a[DD];
__device__ __align__(16) float g_b[DD];

// ---------------- kernel 0: zero scratch (must run every replay) ----------------
__global__ void k_zero() {
    int i = blockIdx.x * blockDim.x + threadIdx.x;
    if (i < GG * DD) {
        g_seg_sum[i] = 0.0f;
        g_seg_sq[i]  = 0.0f;
        g_seg_max[i] = 0;
    }
}

// ---------------- kernel 1: per-segment sum/sumsq/max (single read of tensor) ----
// Block handles a contiguous node range, thread t owns feature t (<300).
// Segments are sorted: accumulate in registers, flush with atomics at boundaries.
__global__ __launch_bounds__(320) void k_seg(const float* __restrict__ x,
                                             const int* __restrict__ seg,
                                             int nodes_per_block) {
    const int t  = threadIdx.x;
    const int n0 = blockIdx.x * nodes_per_block;
    int n1 = n0 + nodes_per_block;
    if (n1 > NN) n1 = NN;
    if (n0 >= NN) return;
    const bool act = (t < DD);

    int   cur = seg[n0];
    float as = 0.0f, aq = 0.0f, am = 0.0f;

    int n = n0;
    while (n < n1) {
        if (n + 4 <= n1) {
            int s0 = seg[n], s1 = seg[n + 1], s2 = seg[n + 2], s3 = seg[n + 3];
            if ((s0 == cur) & (s1 == cur) & (s2 == cur) & (s3 == cur)) {
                if (act) {
                    unsigned base = (unsigned)n * DD + t;
                    float x0 = x[base];
                    float x1 = x[base + DD];
                    float x2 = x[base + 2 * DD];
                    float x3 = x[base + 3 * DD];
                    as += (x0 + x1) + (x2 + x3);
                    aq = fmaf(x0, x0, aq); aq = fmaf(x1, x1, aq);
                    aq = fmaf(x2, x2, aq); aq = fmaf(x3, x3, aq);
                    am = fmaxf(am, fmaxf(fmaxf(fabsf(x0), fabsf(x1)),
                                         fmaxf(fabsf(x2), fabsf(x3))));
                }
                n += 4;
                continue;
            }
        }
        int s = seg[n];
        if (s != cur) {
            if (act) {
                unsigned o = (unsigned)cur * DD + t;
                atomicAdd(&g_seg_sum[o], as);
                atomicAdd(&g_seg_sq[o],  aq);
                atomicMax(&g_seg_max[o], __float_as_int(am));
            }
            cur = s; as = 0.0f; aq = 0.0f; am = 0.0f;
        }
        if (act) {
            float v = x[(unsigned)n * DD + t];
            as += v;
            aq = fmaf(v, v, aq);
            am = fmaxf(am, fabsf(v));
        }
        n++;
    }
    if (act) {
        unsigned o = (unsigned)cur * DD + t;
        atomicAdd(&g_seg_sum[o], as);
        atomicAdd(&g_seg_sq[o],  aq);
        atomicMax(&g_seg_max[o], __float_as_int(am));
    }
}

// ---------------- kernel 2: per-graph scalar scale ----------------
__global__ __launch_bounds__(128) void k_scale() {
    const int g = blockIdx.x;
    const int t = threadIdx.x;
    float m = 0.0f;
    for (int d = t; d < DD; d += 128)
        m = fmaxf(m, __int_as_float(g_seg_max[g * DD + d]));
    // warp reduce
    for (int off = 16; off > 0; off >>= 1)
        m = fmaxf(m, __shfl_xor_sync(0xFFFFFFFFu, m, off));
    __shared__ float sm[4];
    if ((t & 31) == 0) sm[t >> 5] = m;
    __syncthreads();
    if (t == 0) {
        m = fmaxf(fmaxf(sm[0], sm[1]), fmaxf(sm[2], sm[3]));
        m = fmaxf(m, EPS_MAX_F);           // clamp
        g_inv1[g] = rsqrtf(m);             // x *= 1/sqrt(m)
        g_inv2[g] = 1.0f / m;              // x^2 *= 1/m
    }
}

// ---------------- kernel 3: global mean/var per feature -> a[d], b[d] ----------
__global__ __launch_bounds__(256) void k_stats(const float* __restrict__ w,
                                               const float* __restrict__ bias) {
    const int d = blockIdx.x;
    const int t = threadIdx.x;
    float s1 = 0.0f, s2 = 0.0f;
    for (int g = t; g < GG; g += 256) {
        float i1 = g_inv1[g];
        float i2 = g_inv2[g];
        s1 = fmaf(g_seg_sum[g * DD + d], i1, s1);
        s2 = fmaf(g_seg_sq [g * DD + d], i2, s2);
    }
    __shared__ float sh1[256], sh2[256];
    sh1[t] = s1; sh2[t] = s2;
    __syncthreads();
    for (int off = 128; off > 0; off >>= 1) {
        if (t < off) { sh1[t] += sh1[t + off]; sh2[t] += sh2[t + off]; }
        __syncthreads();
    }
    if (t == 0) {
        float S1 = sh1[0], S2 = sh2[0];
        float mean = S1 / (float)NN;
        float var  = (S2 - S1 * S1 / (float)NN) / (float)(NN - 1);
        float rstd = rsqrtf(var + EPS_BN_F);
        float a = w[d] * rstd;
        g_a[d] = a;
        g_b[d] = fmaf(-a, mean, bias[d]);
    }
}

// ---------------- kernel 4: elementwise output (float4) ----------------
__global__ __launch_bounds__(256) void k_out(const float4* __restrict__ x4,
                                             const int* __restrict__ seg,
                                             float4* __restrict__ o4) {
    unsigned i = blockIdx.x * 256u + threadIdx.x;
    if (i >= (unsigned)TOT4) return;
    unsigned n = i / D4;
    unsigned c = i - n * D4;
    float inv = __ldg(&g_inv1[__ldg(&seg[n])]);
    float4 v = x4[i];
    float4 a = ((const float4*)g_a)[c];
    float4 b = ((const float4*)g_b)[c];
    float4 r;
    r.x = fmaf(v.x * inv, a.x, b.x);
    r.y = fmaf(v.y * inv, a.y, b.y);
    r.z = fmaf(v.z * inv, a.z, b.z);
    r.w = fmaf(v.w * inv, a.w, b.w);
    o4[i] = r;
}

extern "C" void kernel_launch(void* const* d_in, const int* in_sizes, int n_in,
                              void* d_out, int out_size) {
    const float* tensor = (const float*)d_in[0];
    const float* weight = (const float*)d_in[1];
    const float* bias   = (const float*)d_in[2];
    const int*   seg    = (const int*)d_in[3];
    float* out = (float*)d_out;

    (void)in_sizes; (void)n_in; (void)out_size;

    // 0: zero scratch
    k_zero<<<(GG * DD + 255) / 256, 256>>>();

    // 1: segment reductions (single read of the 491 MB tensor)
    const int nodes_per_block = 200;
    const int nblocks = (NN + nodes_per_block - 1) / nodes_per_block; // 2048
    k_seg<<<nblocks, 320>>>(tensor, seg, nodes_per_block);

    // 2: per-graph scale
    k_scale<<<GG, 128>>>();

    // 3: global stats -> a[d], b[d]
    k_stats<<<DD, 256>>>(weight, bias);

    // 4: output pass (read + write)
    k_out<<<(TOT4 + 255) / 256, 256>>>((const float4*)tensor, seg, (float4*)out);
}

// round 4
// speedup vs baseline: 1.1106x; 1.1106x over previous
#include <cuda_runtime.h>

#define NN 409600
#define GG 1024
#define DD 300
#define D4 75                 // DD/4 float4 per row
#define TOT4 (NN * D4)        // 30,720,000
#define SPLIT 2               // sub-blocks per segment
#define P75 (GG * D4)         // 76800 float4 per partial slab

static __constant__ float EPS_MAX_F = 1e-12f;
static __constant__ float EPS_BN_F  = 1e-5f;

// ---- scratch (__device__ globals; all fully overwritten each replay) ----
__device__ int    g_start[GG + 1];
__device__ float4 g_psum[SPLIT * P75];   // 2.45 MB
__device__ float4 g_psq [SPLIT * P75];   // 2.45 MB
__device__ float4 g_pmax[SPLIT * P75];   // 2.45 MB
__device__ float  g_inv1[GG];            // 1/sqrt(m)
__device__ float  g_inv2[GG];            // 1/m
__device__ __align__(16) float g_a[DD];
__device__ __align__(16) float g_b[DD];

// ---------------- kernel A: segment boundaries (binary search) ----------------
__global__ void k_bounds(const int* __restrict__ seg) {
    int g = blockIdx.x * blockDim.x + threadIdx.x;
    if (g > GG) return;
    int lo = 0, hi = NN;
    while (lo < hi) {
        int mid = (lo + hi) >> 1;
        if (seg[mid] < g) lo = mid + 1; else hi = mid;
    }
    g_start[g] = lo;
}

// ---------------- kernel B: per-segment sum/sumsq/max, float4, no atomics ------
// grid = GG*SPLIT. block b: g = b>>1, part = b&1. 320 threads, 300 active:
// tx = col (0..74, one float4 of features), ty = row phase (0..3).
__global__ __launch_bounds__(320) void k_seg(const float4* __restrict__ x4) {
    const int t = threadIdx.x;
    const int b = blockIdx.x;
    const int g = b >> 1, part = b & 1;
    const int s = g_start[g];
    const int e = g_start[g + 1];
    const int chunk = (e - s + SPLIT - 1) / SPLIT;
    const int n0 = s + part * chunk;
    const int n1 = min(n0 + chunk, e);

    const bool act = (t < 300);
    const int tx = act ? (t % 75) : 0;
    const int ty = act ? (t / 75) : 0;

    float4 sm = make_float4(0.f, 0.f, 0.f, 0.f);
    float4 sq = make_float4(0.f, 0.f, 0.f, 0.f);
    float4 mx = make_float4(0.f, 0.f, 0.f, 0.f);

    if (act) {
        #pragma unroll 2
        for (int n = n0 + ty; n < n1; n += 4) {
            float4 v = x4[(unsigned)n * 75u + tx];
            sm.x += v.x; sm.y += v.y; sm.z += v.z; sm.w += v.w;
            sq.x = fmaf(v.x, v.x, sq.x); sq.y = fmaf(v.y, v.y, sq.y);
            sq.z = fmaf(v.z, v.z, sq.z); sq.w = fmaf(v.w, v.w, sq.w);
            mx.x = fmaxf(mx.x, fabsf(v.x)); mx.y = fmaxf(mx.y, fabsf(v.y));
            mx.z = fmaxf(mx.z, fabsf(v.z)); mx.w = fmaxf(mx.w, fabsf(v.w));
        }
    }

    __shared__ float4 sh[3][300];
    if (act) {
        sh[0][ty * 75 + tx] = sm;
        sh[1][ty * 75 + tx] = sq;
        sh[2][ty * 75 + tx] = mx;
    }
    __syncthreads();

    if (t < 75) {
        float4 a0 = sh[0][t], a1 = sh[0][t + 75], a2 = sh[0][t + 150], a3 = sh[0][t + 225];
        float4 q0 = sh[1][t], q1 = sh[1][t + 75], q2 = sh[1][t + 150], q3 = sh[1][t + 225];
        float4 m0 = sh[2][t], m1 = sh[2][t + 75], m2 = sh[2][t + 150], m3 = sh[2][t + 225];
        float4 S, Q, M;
        S.x = (a0.x + a1.x) + (a2.x + a3.x);
        S.y = (a0.y + a1.y) + (a2.y + a3.y);
        S.z = (a0.z + a1.z) + (a2.z + a3.z);
        S.w = (a0.w + a1.w) + (a2.w + a3.w);
        Q.x = (q0.x + q1.x) + (q2.x + q3.x);
        Q.y = (q0.y + q1.y) + (q2.y + q3.y);
        Q.z = (q0.z + q1.z) + (q2.z + q3.z);
        Q.w = (q0.w + q1.w) + (q2.w + q3.w);
        M.x = fmaxf(fmaxf(m0.x, m1.x), fmaxf(m2.x, m3.x));
        M.y = fmaxf(fmaxf(m0.y, m1.y), fmaxf(m2.y, m3.y));
        M.z = fmaxf(fmaxf(m0.z, m1.z), fmaxf(m2.z, m3.z));
        M.w = fmaxf(fmaxf(m0.w, m1.w), fmaxf(m2.w, m3.w));
        const unsigned o = (unsigned)(part * GG + g) * 75u + t;
        g_psum[o] = S;
        g_psq[o]  = Q;
        g_pmax[o] = M;
    }
}

// ---------------- kernel C: per-graph scalar scale ----------------
__global__ __launch_bounds__(128) void k_scale() {
    const int g = blockIdx.x;
    const int t = threadIdx.x;
    float m = 0.0f;
    for (int idx = t; idx < SPLIT * 75; idx += 128) {
        int part = idx / 75, c = idx - part * 75;
        float4 v = g_pmax[(unsigned)(part * GG + g) * 75u + c];
        m = fmaxf(m, fmaxf(fmaxf(v.x, v.y), fmaxf(v.z, v.w)));
    }
    for (int off = 16; off > 0; off >>= 1)
        m = fmaxf(m, __shfl_xor_sync(0xFFFFFFFFu, m, off));
    __shared__ float sm[4];
    if ((t & 31) == 0) sm[t >> 5] = m;
    __syncthreads();
    if (t == 0) {
        m = fmaxf(fmaxf(sm[0], sm[1]), fmaxf(sm[2], sm[3]));
        m = fmaxf(m, EPS_MAX_F);
        g_inv1[g] = rsqrtf(m);
        g_inv2[g] = 1.0f / m;
    }
}

// ---------------- kernel D: global mean/var -> a[d], b[d] (float4 per block) ---
__global__ __launch_bounds__(256) void k_stats(const float* __restrict__ w,
                                               const float* __restrict__ bias) {
    const int c4 = blockIdx.x;   // 0..74
    const int t  = threadIdx.x;
    float4 s1 = make_float4(0.f, 0.f, 0.f, 0.f);
    float4 s2 = make_float4(0.f, 0.f, 0.f, 0.f);
    for (int idx = t; idx < SPLIT * GG; idx += 256) {    // idx = part*GG + g
        int g = idx & (GG - 1);
        float i1 = g_inv1[g];
        float i2 = g_inv2[g];
        float4 p = g_psum[(unsigned)idx * 75u + c4];
        float4 q = g_psq [(unsigned)idx * 75u + c4];
        s1.x = fmaf(p.x, i1, s1.x); s1.y = fmaf(p.y, i1, s1.y);
        s1.z = fmaf(p.z, i1, s1.z); s1.w = fmaf(p.w, i1, s1.w);
        s2.x = fmaf(q.x, i2, s2.x); s2.y = fmaf(q.y, i2, s2.y);
        s2.z = fmaf(q.z, i2, s2.z); s2.w = fmaf(q.w, i2, s2.w);
    }
    __shared__ float4 sh1[256], sh2[256];
    sh1[t] = s1; sh2[t] = s2;
    __syncthreads();
    for (int off = 128; off > 0; off >>= 1) {
        if (t < off) {
            float4 a = sh1[t], b4 = sh1[t + off];
            a.x += b4.x; a.y += b4.y; a.z += b4.z; a.w += b4.w;
            sh1[t] = a;
            float4 c = sh2[t], d4 = sh2[t + off];
            c.x += d4.x; c.y += d4.y; c.z += d4.z; c.w += d4.w;
            sh2[t] = c;
        }
        __syncthreads();
    }
    if (t == 0) {
        float S1a[4] = {sh1[0].x, sh1[0].y, sh1[0].z, sh1[0].w};
        float S2a[4] = {sh2[0].x, sh2[0].y, sh2[0].z, sh2[0].w};
        #pragma unroll
        for (int k = 0; k < 4; k++) {
            int d = c4 * 4 + k;
            float S1 = S1a[k], S2 = S2a[k];
            float mean = S1 / (float)NN;
            float var  = (S2 - S1 * S1 / (float)NN) / (float)(NN - 1);
            float rstd = rsqrtf(var + EPS_BN_F);
            float a = w[d] * rstd;
            g_a[d] = a;
            g_b[d] = fmaf(-a, mean, bias[d]);
        }
    }
}

// ---------------- kernel E: elementwise output, reversed block order ----------
// Reversed so the tensor TAIL (still resident in L2 from k_seg) is read first.
__global__ __launch_bounds__(256) void k_out(const float4* __restrict__ x4,
                                             const int* __restrict__ seg,
                                             float4* __restrict__ o4) {
    unsigned j = gridDim.x - 1u - blockIdx.x;
    unsigned i = j * 256u + threadIdx.x;
    if (i >= (unsigned)TOT4) return;
    unsigned n = i / 75u;
    unsigned c = i - n * 75u;
    float inv = __ldg(&g_inv1[__ldg(&seg[n])]);
    float4 v = x4[i];
    float4 a = ((const float4*)g_a)[c];
    float4 b = ((const float4*)g_b)[c];
    float4 r;
    r.x = fmaf(v.x * inv, a.x, b.x);
    r.y = fmaf(v.y * inv, a.y, b.y);
    r.z = fmaf(v.z * inv, a.z, b.z);
    r.w = fmaf(v.w * inv, a.w, b.w);
    o4[i] = r;
}

extern "C" void kernel_launch(void* const* d_in, const int* in_sizes, int n_in,
                              void* d_out, int out_size) {
    const float* tensor = (const float*)d_in[0];
    const float* weight = (const float*)d_in[1];
    const float* bias   = (const float*)d_in[2];
    const int*   seg    = (const int*)d_in[3];
    float* out = (float*)d_out;
    (void)in_sizes; (void)n_in; (void)out_size;

    k_bounds<<<5, 256>>>(seg);
    k_seg<<<GG * SPLIT, 320>>>((const float4*)tensor);
    k_scale<<<GG, 128>>>();
    k_stats<<<D4, 256>>>(weight, bias);
    k_out<<<(TOT4 + 255) / 256, 256>>>((const float4*)tensor, seg, (float4*)out);
}